// round 9
// baseline (speedup 1.0000x reference)
#include <cuda_runtime.h>
#include <math.h>

#define NN 100000
#define NE 2000000
#define INC 30
#define HID 40
#define D1 20
#define D2 10
#define NCLS 3
#define NB_EDGE ((NE + 255) / 256)       // 7813
#define NB_NODE ((NN + 255) / 256)       // 391
#define NB_SPT  ((NN + 1023) / 1024)     // 98
#define CAND_OFF 1024

// out layout: logits[3], Y_prob[3], Y_hat[1], A[NN], x3[NN*D1], cell_loss[1]
#define OUT_A 7
#define OUT_X3 (7 + NN)
#define OUT_LOSS (7 + NN + NN * D1)

#define FINF  __int_as_float(0x7f800000)
#define FNINF __int_as_float(0xff800000)

// ---------------- scratch ----------------
__device__ __align__(16) float g_h[NN * HID];    // layer-1 input features
__device__ __align__(16) float g_hB[NN * HID];   // layer-2 input features (double buffer)
__device__ __align__(16) float g_x3[NN * D1];
__device__ float g_a[NN];
__device__ unsigned long long g_dc[NN];   // packed cnt<<40 | deg*2^28 (zero on entry; re-zeroed in scan3)
__device__ float g_dinv[NN];
__device__ int   g_pref[NN];
__device__ int   g_bsum[128];
__device__ int   g_rowstart[NN + 1];
__device__ int   g_cur[NN];
__device__ unsigned long long g_csr[NE];
__device__ float g_bm[128];
__device__ float g_bs[128];
__device__ float g_bp[128 * D1];
__device__ float g_gmax;
__device__ float g_denom;
__device__ float g_pooled[D1];
__device__ float g_cand_v[2 * CAND_OFF];
__device__ int   g_cand_i[2 * CAND_OFF];
__device__ unsigned int g_done;           // zero on entry; re-zeroed in final

// ---------------- helpers ----------------
__device__ __forceinline__ float selu_f(float x) {
    const float sc = 1.0507009873554805f, al = 1.6732632423543772f;
    return x > 0.f ? sc * x : sc * al * expm1f(x);
}
__device__ __forceinline__ int clampn(int v) {
    return v < 0 ? 0 : (v >= NN ? NN - 1 : v);
}
__device__ __forceinline__ float warp_sum(float v) {
#pragma unroll
    for (int off = 16; off; off >>= 1) v += __shfl_down_sync(0xffffffffu, v, off);
    return __shfl_sync(0xffffffffu, v, 0);
}

__device__ __forceinline__ void decode_edge(const void* eiv, bool is64, int e,
                                            int& s, int& d) {
    if (is64) {
        const long long* ei = (const long long*)eiv;
        s = (int)ei[e]; d = (int)ei[NE + e];
    } else {
        const int* ei = (const int*)eiv;
        s = ei[e]; d = ei[NE + e];
    }
    s = clampn(s); d = clampn(d);
}
__device__ __forceinline__ bool detect64(const void* eiv) {
    __shared__ int any_nz;
    if (threadIdx.x == 0) any_nz = 0;
    __syncthreads();
    if (((const int*)eiv)[2 * threadIdx.x + 1] != 0) atomicOr(&any_nz, 1);
    __syncthreads();
    return any_nz == 0;
}

// ---------------- kernels ----------------
// blocks [0, NB_EDGE): edge prep (packed deg/cnt atomic)
// blocks [NB_EDGE, ...): h = x @ W1
__global__ void k_prepmm(const void* __restrict__ eiv, const float* __restrict__ ew,
                         const float* __restrict__ X, const float* __restrict__ W) {
    if (blockIdx.x < NB_EDGE) {
        bool is64 = detect64(eiv);
        int e = blockIdx.x * 256 + threadIdx.x;
        if (e >= NE) return;
        int s, d;
        decode_edge(eiv, is64, e, s, d);
        (void)s;
        unsigned long long fx = (unsigned long long)(ew[e] * 268435456.0f + 0.5f);
        atomicAdd(&g_dc[d], (1ULL << 40) | fx);
    } else {
        __shared__ float sW[INC * HID];
        for (int i = threadIdx.x; i < INC * HID; i += 256) sW[i] = W[i];
        __syncthreads();
        int n = (blockIdx.x - NB_EDGE) * 256 + threadIdx.x;
        if (n >= NN) return;
        float acc[HID];
#pragma unroll
        for (int o = 0; o < HID; o++) acc[o] = 0.f;
        const float* xr = X + (long)n * INC;
#pragma unroll
        for (int k = 0; k < INC; k++) {
            float xv = __ldg(xr + k);
#pragma unroll
            for (int o = 0; o < HID; o++) acc[o] += xv * sW[k * HID + o];
        }
        float* yr = g_h + (long)n * HID;
#pragma unroll
        for (int o = 0; o < HID; o++) yr[o] = acc[o];
    }
}

// block-local exclusive scan of counts
__global__ void k_scan1() {
    __shared__ int sm[1024];
    int t = threadIdx.x;
    int gid = blockIdx.x * 1024 + t;
    int x = (gid < NN) ? (int)(g_dc[gid] >> 40) : 0;
    sm[t] = x; __syncthreads();
    for (int off = 1; off < 1024; off <<= 1) {
        int v = (t >= off) ? sm[t - off] : 0;
        __syncthreads();
        sm[t] += v;
        __syncthreads();
    }
    if (gid < NN) g_pref[gid] = sm[t] - x;
    if (t == 1023) g_bsum[blockIdx.x] = sm[1023];
}

// add block offsets + rowstart/cur/dinv; re-zero g_dc for next replay
__global__ void k_scan3(int nblk) {
    __shared__ int sb[128];
    __shared__ int soff;
    int t = threadIdx.x;
    if (t < 128) sb[t] = (t < nblk) ? g_bsum[t] : 0;
    __syncthreads();
    if (t == 0) {
        int s = 0;
        for (int j = 0; j < blockIdx.x; j++) s += sb[j];
        soff = s;
    }
    __syncthreads();
    int gid = blockIdx.x * 1024 + t;
    if (gid < NN) {
        int rs = g_pref[gid] + soff;
        g_rowstart[gid] = rs;
        g_cur[gid] = rs;
        unsigned long long dc = g_dc[gid];
        float deg = (float)(dc & ((1ULL << 40) - 1ULL)) * (1.0f / 268435456.0f);
        g_dinv[gid] = rsqrtf(deg + 1.0f);
        g_dc[gid] = 0ULL;
    }
    if (gid == 0) g_rowstart[NN] = NE;
}

// build CSR entries (src, norm) packed 8B; re-decodes edge_index
__global__ void k_scatter(const void* __restrict__ eiv, const float* __restrict__ ew) {
    bool is64 = detect64(eiv);
    int e = blockIdx.x * 256 + threadIdx.x;
    if (e >= NE) return;
    int s, d;
    decode_edge(eiv, is64, e, s, d);
    float w = g_dinv[s] * ew[e] * g_dinv[d];
    int pos = atomicAdd(&g_cur[d], 1);
    g_csr[pos] = ((unsigned long long)__float_as_uint(w) << 32) | (unsigned int)s;
}

// ---- warp aggregation from hsrc + LN + selu -> xv4 (lanes 0-9 x float4)
__device__ __forceinline__ void warp_agg_ln(const float* __restrict__ hsrc, int node,
                                            const float* b, const float* lw,
                                            const float* lb, int lane, float xv4[4]) {
    int grp = lane / 10;          // 0..2 active, 3 idle
    int chunk = lane - grp * 10;  // 0..9
    bool act = lane < 30;
    int beg = g_rowstart[node], end = g_rowstart[node + 1];
    const float4* h4 = reinterpret_cast<const float4*>(hsrc);
    float4 acc = make_float4(0.f, 0.f, 0.f, 0.f);
    int ee = beg + grp;
    unsigned long long ent = (act && ee < end) ? __ldg(&g_csr[ee]) : 0ULL;
    for (int e = beg; e < end; e += 3) {
        bool curv = act && (e + grp) < end;
        unsigned long long cur = ent;
        int en = e + 3 + grp;
        ent = (act && en < end) ? __ldg(&g_csr[en]) : 0ULL;
        if (curv) {
            int s = (int)(unsigned int)cur;
            float w = __uint_as_float((unsigned int)(cur >> 32));
            float4 v = __ldg(h4 + s * 10 + chunk);
            acc.x += v.x * w; acc.y += v.y * w;
            acc.z += v.z * w; acc.w += v.w * w;
        }
    }
    float rx = acc.x + __shfl_down_sync(0xffffffffu, acc.x, 10)
                     + __shfl_down_sync(0xffffffffu, acc.x, 20);
    float ry = acc.y + __shfl_down_sync(0xffffffffu, acc.y, 10)
                     + __shfl_down_sync(0xffffffffu, acc.y, 20);
    float rz = acc.z + __shfl_down_sync(0xffffffffu, acc.z, 10)
                     + __shfl_down_sync(0xffffffffu, acc.z, 20);
    float rw = acc.w + __shfl_down_sync(0xffffffffu, acc.w, 10)
                     + __shfl_down_sync(0xffffffffu, acc.w, 20);
    float4 r = make_float4(0.f, 0.f, 0.f, 0.f);
    if (lane < 10) {
        float di = g_dinv[node], d2 = di * di;
        float4 hv = h4[node * 10 + lane];
        float4 bv = __ldg(reinterpret_cast<const float4*>(b) + lane);
        r.x = rx + hv.x * d2 + bv.x;
        r.y = ry + hv.y * d2 + bv.y;
        r.z = rz + hv.z * d2 + bv.z;
        r.w = rw + hv.w * d2 + bv.w;
    }
    float ls = (lane < 10) ? (r.x + r.y + r.z + r.w) : 0.f;
    float m = warp_sum(ls) * (1.0f / HID);
    float lv = 0.f;
    if (lane < 10) {
        float dx = r.x - m, dy = r.y - m, dz = r.z - m, dw = r.w - m;
        lv = dx * dx + dy * dy + dz * dz + dw * dw;
    }
    float inv = rsqrtf(warp_sum(lv) * (1.0f / HID) + 1e-5f);
    xv4[0] = xv4[1] = xv4[2] = xv4[3] = 0.f;
    if (lane < 10) {
        float4 w4 = __ldg(reinterpret_cast<const float4*>(lw) + lane);
        float4 b4 = __ldg(reinterpret_cast<const float4*>(lb) + lane);
        xv4[0] = selu_f((r.x - m) * inv * w4.x + b4.x);
        xv4[1] = selu_f((r.y - m) * inv * w4.y + b4.y);
        xv4[2] = selu_f((r.z - m) * inv * w4.z + b4.z);
        xv4[3] = selu_f((r.w - m) * inv * w4.w + b4.w);
    }
}

// layer 1: agg(g_h) + LN + selu + (x1 @ W2) -> g_hB (double buffer, no race)
__global__ void k_layer1(const float* __restrict__ b1, const float* __restrict__ lw,
                         const float* __restrict__ lb, const float* __restrict__ W2) {
    int node = blockIdx.x * 16 + (threadIdx.x >> 5);
    if (node >= NN) return;
    int lane = threadIdx.x & 31;
    float xv4[4];
    warp_agg_ln(g_h, node, b1, lw, lb, lane, xv4);
    float acc = 0.f, acc2 = 0.f;
#pragma unroll
    for (int k = 0; k < HID; k++) {
        float xv = __shfl_sync(0xffffffffu, xv4[k & 3], k >> 2);
        acc += xv * __ldg(W2 + k * HID + lane);
        if (lane < 8) acc2 += xv * __ldg(W2 + k * HID + 32 + lane);
    }
    g_hB[node * HID + lane] = acc;
    if (lane < 8) g_hB[node * HID + 32 + lane] = acc2;
}

// layer 2: agg(g_hB) + LN + selu + FNN(x3) + attention score
__global__ void k_layer2(const float* __restrict__ b2, const float* __restrict__ lw,
                         const float* __restrict__ lb, const float* __restrict__ Wf,
                         const float* __restrict__ bf, const float* __restrict__ Wt,
                         const float* __restrict__ bt, const float* __restrict__ Ws,
                         const float* __restrict__ bs, const float* __restrict__ Wc,
                         const float* __restrict__ bc, float* __restrict__ outx3) {
    int node = blockIdx.x * 16 + (threadIdx.x >> 5);
    if (node >= NN) return;
    int lane = threadIdx.x & 31;
    float xv4[4];
    warp_agg_ln(g_hB, node, b2, lw, lb, lane, xv4);
    float x3 = (lane < D1) ? __ldg(bf + lane) : 0.f;
#pragma unroll
    for (int k = 0; k < HID; k++) {
        float xv = __shfl_sync(0xffffffffu, xv4[k & 3], k >> 2);
        if (lane < D1) x3 += xv * __ldg(Wf + k * D1 + lane);
    }
    if (lane < D1) {
        x3 = selu_f(x3);
        g_x3[node * D1 + lane] = x3;
        outx3[node * D1 + lane] = x3;
    }
    float zt = (lane < D2) ? __ldg(bt + lane) : 0.f;
    float zs = (lane < D2) ? __ldg(bs + lane) : 0.f;
#pragma unroll
    for (int k = 0; k < D1; k++) {
        float xv = __shfl_sync(0xffffffffu, x3, k);
        if (lane < D2) {
            zt += xv * __ldg(Wt + k * D2 + lane);
            zs += xv * __ldg(Ws + k * D2 + lane);
        }
    }
    float contrib = 0.f;
    if (lane < D2)
        contrib = tanhf(zt) * (1.f / (1.f + expf(-zs))) * __ldg(Wc + lane);
    float total = warp_sum(contrib);
    if (lane == 0) g_a[node] = __ldg(bc) + total;
}

// softmax partials + pooled partials + per-block top/bot-8 candidates;
// last block finalizes gmax/denom/pooled.
__global__ void k_sptk() {
    __shared__ float sv[1024];
    __shared__ int si[1024];
    __shared__ float spool[32][D1];
    __shared__ bool isLast;
    int t = threadIdx.x;
    int wid = t >> 5, lane = t & 31;
    int gid = blockIdx.x * 1024 + t;
    bool valid = gid < NN;
    float a = valid ? g_a[gid] : FNINF;
    sv[t] = a; __syncthreads();
    for (int st = 512; st > 0; st >>= 1) {
        if (t < st) sv[t] = fmaxf(sv[t], sv[t + st]);
        __syncthreads();
    }
    float mb = sv[0];
    __syncthreads();
    float w = valid ? expf(a - mb) : 0.f;
    float px[D1];
#pragma unroll
    for (int f = 0; f < D1; f++) px[f] = 0.f;
    if (valid) {
        const float4* xr = reinterpret_cast<const float4*>(g_x3) + gid * (D1 / 4);
#pragma unroll
        for (int j = 0; j < D1 / 4; j++) {
            float4 t4 = __ldg(xr + j);
            px[4 * j + 0] = w * t4.x; px[4 * j + 1] = w * t4.y;
            px[4 * j + 2] = w * t4.z; px[4 * j + 3] = w * t4.w;
        }
    }
#pragma unroll
    for (int f = 0; f < D1; f++) {
        float vv = px[f];
#pragma unroll
        for (int off = 16; off; off >>= 1) vv += __shfl_down_sync(0xffffffffu, vv, off);
        if (lane == 0) spool[wid][f] = vv;
    }
    sv[t] = w; __syncthreads();
    for (int st = 512; st > 0; st >>= 1) {
        if (t < st) sv[t] += sv[t + st];
        __syncthreads();
    }
    if (t == 0) { g_bm[blockIdx.x] = mb; g_bs[blockIdx.x] = sv[0]; }
    __syncthreads();
    if (t < D1) {
        float s = 0.f;
        for (int j = 0; j < 32; j++) s += spool[j][t];
        g_bp[blockIdx.x * D1 + t] = s;
    }
    float vt = valid ? a : FNINF;
    float vb = valid ? a : FINF;
    int myi = valid ? gid : 0x7fffffff;
    for (int pass = 0; pass < 8; pass++) {
        __syncthreads();
        sv[t] = vt; si[t] = myi; __syncthreads();
        for (int st = 512; st > 0; st >>= 1) {
            if (t < st) {
                float v2 = sv[t + st]; int i2 = si[t + st];
                if (v2 > sv[t] || (v2 == sv[t] && i2 < si[t])) { sv[t] = v2; si[t] = i2; }
            }
            __syncthreads();
        }
        if (t == 0) {
            g_cand_v[blockIdx.x * 8 + pass] = sv[0];
            g_cand_i[blockIdx.x * 8 + pass] = si[0];
        }
        if (myi == si[0]) vt = FNINF;
    }
    for (int pass = 0; pass < 8; pass++) {
        __syncthreads();
        sv[t] = vb; si[t] = myi; __syncthreads();
        for (int st = 512; st > 0; st >>= 1) {
            if (t < st) {
                float v2 = sv[t + st]; int i2 = si[t + st];
                if (v2 < sv[t] || (v2 == sv[t] && i2 < si[t])) { sv[t] = v2; si[t] = i2; }
            }
            __syncthreads();
        }
        if (t == 0) {
            g_cand_v[CAND_OFF + blockIdx.x * 8 + pass] = sv[0];
            g_cand_i[CAND_OFF + blockIdx.x * 8 + pass] = si[0];
        }
        if (myi == si[0]) vb = FINF;
    }
    __threadfence();
    if (t == 0) isLast = (atomicAdd(&g_done, 1u) == NB_SPT - 1);
    __syncthreads();
    if (!isLast) return;
    __threadfence();
    float mt = (t < NB_SPT) ? g_bm[t] : FNINF;
    sv[t] = mt; __syncthreads();
    for (int st = 512; st > 0; st >>= 1) {
        if (t < st) sv[t] = fmaxf(sv[t], sv[t + st]);
        __syncthreads();
    }
    float M = sv[0];
    __syncthreads();
    float scale = (t < NB_SPT) ? expf(mt - M) : 0.f;
    sv[t] = (t < NB_SPT) ? g_bs[t] * scale : 0.f;
    __syncthreads();
    for (int st = 512; st > 0; st >>= 1) {
        if (t < st) sv[t] += sv[t + st];
        __syncthreads();
    }
    float denom = sv[0];
    if (t == 0) { g_gmax = M; g_denom = denom; }
    __syncthreads();
    for (int f = 0; f < D1; f++) {
        sv[t] = (t < NB_SPT) ? g_bp[t * D1 + f] * scale : 0.f;
        __syncthreads();
        for (int st = 512; st > 0; st >>= 1) {
            if (t < st) sv[t] += sv[t + st];
            __syncthreads();
        }
        if (t == 0) g_pooled[f] = sv[0] / denom;
        __syncthreads();
    }
}

// block 0: merge candidates + tail math; blocks 1..NB_SPT: write A
__global__ void k_final(const float* __restrict__ Wcls, const float* __restrict__ bcls,
                        const float* __restrict__ Wcell, const float* __restrict__ bcell,
                        const int* __restrict__ labelp, float* __restrict__ out) {
    int t = threadIdx.x;
    if (blockIdx.x > 0) {
        int gid = (blockIdx.x - 1) * 1024 + t;
        if (gid < NN) out[OUT_A + gid] = expf(g_a[gid] - g_gmax) / g_denom;
        return;
    }
    __shared__ float sv[1024];
    __shared__ int si[1024];
    __shared__ int ssel[16];
    const int NC = NB_SPT * 8;  // 784
    float vt = (t < NC) ? g_cand_v[t] : FNINF;
    int it = (t < NC) ? g_cand_i[t] : 0x7fffffff;
    for (int pass = 0; pass < 8; pass++) {
        __syncthreads();
        sv[t] = vt; si[t] = it; __syncthreads();
        for (int st = 512; st > 0; st >>= 1) {
            if (t < st) {
                float v2 = sv[t + st]; int i2 = si[t + st];
                if (v2 > sv[t] || (v2 == sv[t] && i2 < si[t])) { sv[t] = v2; si[t] = i2; }
            }
            __syncthreads();
        }
        if (t == 0) ssel[pass] = si[0];
        if (it == si[0]) vt = FNINF;
    }
    float vb = (t < NC) ? g_cand_v[CAND_OFF + t] : FINF;
    int ib = (t < NC) ? g_cand_i[CAND_OFF + t] : 0x7fffffff;
    for (int pass = 0; pass < 8; pass++) {
        __syncthreads();
        sv[t] = vb; si[t] = ib; __syncthreads();
        for (int st = 512; st > 0; st >>= 1) {
            if (t < st) {
                float v2 = sv[t + st]; int i2 = si[t + st];
                if (v2 < sv[t] || (v2 == sv[t] && i2 < si[t])) { sv[t] = v2; si[t] = i2; }
            }
            __syncthreads();
        }
        if (t == 0) ssel[8 + pass] = si[0];
        if (ib == si[0]) vb = FINF;
    }
    __syncthreads();
    if (t != 0) return;
    g_done = 0u;  // reset for next graph replay
    float logits[NCLS];
#pragma unroll
    for (int c = 0; c < NCLS; c++) {
        float s = bcls[c];
#pragma unroll
        for (int f = 0; f < D1; f++) s += g_pooled[f] * Wcls[f * NCLS + c];
        logits[c] = s;
    }
    float mx = fmaxf(logits[0], fmaxf(logits[1], logits[2]));
    float e0 = expf(logits[0] - mx), e1 = expf(logits[1] - mx), e2 = expf(logits[2] - mx);
    float es = e0 + e1 + e2;
    int yhat = 0;
    if (logits[1] > logits[yhat]) yhat = 1;
    if (logits[2] > logits[yhat]) yhat = 2;
    out[0] = logits[0]; out[1] = logits[1]; out[2] = logits[2];
    out[3] = e0 / es; out[4] = e1 / es; out[5] = e2 / es;
    out[6] = (float)yhat;
    int label = labelp[0];
    if (label < 0) label = 0;
    if (label >= NCLS) label = NCLS - 1;
    const float* Wl = Wcell + label * D1 * 2;
    const float* bl = bcell + label * 2;
    float loss = 0.f;
    for (int i = 0; i < 16; i++) {
        int node = ssel[i];
        if (node < 0 || node >= NN) node = 0;
        int tgt = (i < 8) ? 1 : 0;
        const float* xr = g_x3 + (long)node * D1;
        float l0 = bl[0], l1 = bl[1];
#pragma unroll
        for (int f = 0; f < D1; f++) { l0 += xr[f] * Wl[f * 2]; l1 += xr[f] * Wl[f * 2 + 1]; }
        float u0 = l0 + (tgt == 1 ? 1.f : 0.f);
        float u1 = l1 + (tgt == 0 ? 1.f : 0.f);
        float mm = fmaxf(u0, u1);
        float lse = mm + logf(expf(u0 - mm) + expf(u1 - mm));
        float sy = tgt ? l1 : l0;
        loss += lse - sy;
    }
    out[OUT_LOSS] = loss * (1.f / 16.f);
}

// ---------------- launch ----------------
extern "C" void kernel_launch(void* const* d_in, const int* in_sizes, int n_in,
                              void* d_out, int out_size) {
    const float* x = (const float*)d_in[0];
    const void* ei = d_in[1];
    const float* ew = (const float*)d_in[2];
    const int* label = (const int*)d_in[3];
    const float* W1 = (const float*)d_in[4];
    const float* b1 = (const float*)d_in[5];
    const float* ln1w = (const float*)d_in[6];
    const float* ln1b = (const float*)d_in[7];
    const float* W2 = (const float*)d_in[8];
    const float* b2 = (const float*)d_in[9];
    const float* ln2w = (const float*)d_in[10];
    const float* ln2b = (const float*)d_in[11];
    const float* Wf = (const float*)d_in[12];
    const float* bf = (const float*)d_in[13];
    const float* Wt = (const float*)d_in[14];
    const float* bt = (const float*)d_in[15];
    const float* Ws = (const float*)d_in[16];
    const float* bs = (const float*)d_in[17];
    const float* Wc = (const float*)d_in[18];
    const float* bc = (const float*)d_in[19];
    const float* Wcls = (const float*)d_in[20];
    const float* bcls = (const float*)d_in[21];
    const float* Wcell = (const float*)d_in[22];
    const float* bcell = (const float*)d_in[23];
    float* out = (float*)d_out;

    int nb_layer = (NN + 15) / 16;   // 6250 blocks of 512 (16 warps)

    k_prepmm<<<NB_EDGE + NB_NODE, 256>>>(ei, ew, x, W1);
    k_scan1<<<NB_SPT, 1024>>>();
    k_scan3<<<NB_SPT, 1024>>>(NB_SPT);
    k_scatter<<<NB_EDGE, 256>>>(ei, ew);

    k_layer1<<<nb_layer, 512>>>(b1, ln1w, ln1b, W2);
    k_layer2<<<nb_layer, 512>>>(b2, ln2w, ln2b, Wf, bf, Wt, bt, Ws, bs, Wc, bc,
                                out + OUT_X3);

    k_sptk<<<NB_SPT, 1024>>>();
    k_final<<<NB_SPT + 1, 1024>>>(Wcls, bcls, Wcell, bcell, label, out);
}